// round 2
// baseline (speedup 1.0000x reference)
#include <cuda_runtime.h>

#define NN   50000
#define NE   1600000
#define NR   8
#define KC   1152        // NR*128 + 128 (relation means ++ self term)
#define CAP  16384       // max compacted "needed" nodes (expected ~8.4K)
#define NP   256
#define DOUT 64

typedef unsigned long long ull;

// packed fp32x2 FMA (sm_103a): d = a*b + d elementwise on {lo,hi} pairs
#define FMA2(d, a, b) asm("fma.rn.f32x2 %0, %1, %2, %0;" : "+l"(d) : "l"(a), "l"(b))
#define PACK2(d, lo, hi) asm("mov.b64 %0, {%1, %2};" : "=l"(d) : "f"(lo), "f"(hi))
#define UNPK2(lo, hi, d) asm("mov.b64 {%0, %1}, %2;" : "=f"(lo), "=f"(hi) : "l"(d))

// ---- scratch (device globals: no allocation allowed in kernel_launch) ----
__device__ int   g_pmap[NN];          // node is a pooled dst
__device__ int   g_nf[NN];            // node is "needed" (pool or src-of-edge-into-pool)
__device__ int   g_cid[NN];           // node -> compact id
__device__ int   g_nodes[CAP];        // compact id -> node
__device__ int   g_counter;           // number of needed nodes
__device__ int   g_head[NR * NN];     // per (rel,dst) linked-list head (edge index), -1 = empty
__device__ int   g_next[NE];          // linked-list next (indexed by edge id)
__device__ float g_C[(size_t)CAP * KC];   // per needed node: [mean_r0..mean_r7, x[v]] (1152)
__device__ float g_h[(size_t)CAP * 128];  // layer-1 output at needed nodes
__device__ float g_part[NP * DOUT];       // per-pool-slot weighted layer-2 output
__device__ float g_wp[NP];                // per-pool-slot entity weight

// ---------------------------------------------------------------- init
__global__ void k_init() {
    int i = blockIdx.x * blockDim.x + threadIdx.x;
    if (i < NR * NN) g_head[i] = -1;
    if (i < NN) { g_pmap[i] = 0; g_nf[i] = 0; }
    if (i == 0) g_counter = 0;
}

__global__ void k_mark_pool(const int* __restrict__ pool) {
    int p = pool[threadIdx.x];
    g_pmap[p] = 1;
    g_nf[p]   = 1;
}

// mark sources of edges whose dst is pooled (those need h)
__global__ void k_mark_src(const int* __restrict__ ei) {
    int e = blockIdx.x * blockDim.x + threadIdx.x;
    if (e >= NE) return;
    int dst = ei[NE + e];
    if (g_pmap[dst]) g_nf[ei[e]] = 1;
}

__global__ void k_compact() {
    int v = blockIdx.x * blockDim.x + threadIdx.x;
    if (v >= NN) return;
    if (g_nf[v]) {
        int c = atomicAdd(&g_counter, 1);
        if (c < CAP) { g_cid[v] = c; g_nodes[c] = v; }
    }
}

// build per-(rel,dst) linked lists over relevant edges only (dst needed).
__global__ void k_build(const int* __restrict__ ei, const int* __restrict__ et) {
    int e = blockIdx.x * blockDim.x + threadIdx.x;
    if (e >= NE) return;
    int dst = ei[NE + e];
    if (!g_nf[dst]) return;
    int r = et[e];
    g_next[e] = atomicExch(&g_head[r * NN + dst], e);
}

// ------------------------------------------------- layer-1 aggregation
__global__ void k_agg1(const float* __restrict__ x, const int* __restrict__ ei) {
    const float4* x4 = (const float4*)x;
    int wid   = (blockIdx.x * blockDim.x + threadIdx.x) >> 5;
    int lane  = threadIdx.x & 31;
    int nwarp = (gridDim.x * blockDim.x) >> 5;
    int cnt   = min(g_counter, CAP);
    int ntask = cnt * 9;
    for (int t = wid; t < ntask; t += nwarp) {
        int i = t / 9;
        int r = t - i * 9;
        int v = g_nodes[i];
        float4 acc = make_float4(0.f, 0.f, 0.f, 0.f);
        if (r == 8) {
            acc = x4[v * 32 + lane];
        } else {
            int ptr = g_head[r * NN + v];
            int c = 0;
            while (ptr >= 0) {
                int src = ei[ptr];
                float4 xv = x4[src * 32 + lane];
                acc.x += xv.x; acc.y += xv.y; acc.z += xv.z; acc.w += xv.w;
                c++;
                ptr = g_next[ptr];
            }
            if (c > 1) {
                float s = 1.0f / (float)c;
                acc.x *= s; acc.y *= s; acc.z *= s; acc.w *= s;
            }
        }
        *(float4*)&g_C[(size_t)i * KC + r * 128 + lane * 4] = acc;
    }
}

// ------------------------------------------------- layer-1 GEMM + relu
// h = relu(C @ [W1;root1] + b1). M=n_needed, N=128, K=1152.
// Block tile 64x128, 128 threads (16 colgroups x 8 rowgroups), 8x8 microtile.
// FFMA2 (fp32x2) inner product; A row-pairs read as 64-bit LDS directly.
__global__ void __launch_bounds__(128) k_gemm1(const float* __restrict__ W1,
                                               const float* __restrict__ root1,
                                               const float* __restrict__ b1) {
    __shared__ __align__(16) float Cs[32 * 66];    // [k][row], stride 66
    __shared__ __align__(16) float Ws[32 * 128];   // [k][col]
    int cnt  = min(g_counter, CAP);
    int row0 = blockIdx.x * 64;
    if (row0 >= cnt) return;
    int t  = threadIdx.x;
    int cg = t & 15;   // cols cg*8 .. cg*8+7
    int rg = t >> 4;   // rows rg*8 .. rg*8+7

    ull acc[4][8];     // [row-pair][col], packed {row 2i, row 2i+1}
#pragma unroll
    for (int i = 0; i < 4; i++)
#pragma unroll
        for (int j = 0; j < 8; j++) acc[i][j] = 0ull;

    for (int kc = 0; kc < KC / 32; kc++) {
        // stage C tile (64 rows x 32 k) transposed to Cs[k][row]
#pragma unroll
        for (int q = 0; q < 4; q++) {
            int idx = t + q * 128;
            int row = idx >> 3, k4 = idx & 7;
            int gr = row0 + row;
            float4 v = (gr < cnt) ? *(const float4*)&g_C[(size_t)gr * KC + kc * 32 + k4 * 4]
                                  : make_float4(0.f, 0.f, 0.f, 0.f);
            Cs[(k4 * 4 + 0) * 66 + row] = v.x;
            Cs[(k4 * 4 + 1) * 66 + row] = v.y;
            Cs[(k4 * 4 + 2) * 66 + row] = v.z;
            Cs[(k4 * 4 + 3) * 66 + row] = v.w;
        }
        // stage W slab (32 k x 128 cols)
#pragma unroll
        for (int q = 0; q < 8; q++) {
            int idx = t + q * 128;          // float4 index
            int k = idx >> 5, c4 = idx & 31;
            int gk = kc * 32 + k;
            float4 wv = (gk < 1024) ? *(const float4*)&W1[gk * 128 + c4 * 4]
                                    : *(const float4*)&root1[(gk - 1024) * 128 + c4 * 4];
            *(float4*)&Ws[k * 128 + c4 * 4] = wv;
        }
        __syncthreads();
#pragma unroll 8
        for (int k = 0; k < 32; k++) {
            const ull* ap = (const ull*)&Cs[k * 66 + rg * 8];
            ull a0 = ap[0], a1 = ap[1], a2 = ap[2], a3 = ap[3];
            float4 bl = *(const float4*)&Ws[k * 128 + cg * 8];
            float4 bh = *(const float4*)&Ws[k * 128 + cg * 8 + 4];
            ull b0, b1p, b2, b3, b4, b5, b6, b7;
            PACK2(b0, bl.x, bl.x); PACK2(b1p, bl.y, bl.y);
            PACK2(b2, bl.z, bl.z); PACK2(b3, bl.w, bl.w);
            PACK2(b4, bh.x, bh.x); PACK2(b5, bh.y, bh.y);
            PACK2(b6, bh.z, bh.z); PACK2(b7, bh.w, bh.w);
            FMA2(acc[0][0], a0, b0); FMA2(acc[0][1], a0, b1p);
            FMA2(acc[0][2], a0, b2); FMA2(acc[0][3], a0, b3);
            FMA2(acc[0][4], a0, b4); FMA2(acc[0][5], a0, b5);
            FMA2(acc[0][6], a0, b6); FMA2(acc[0][7], a0, b7);
            FMA2(acc[1][0], a1, b0); FMA2(acc[1][1], a1, b1p);
            FMA2(acc[1][2], a1, b2); FMA2(acc[1][3], a1, b3);
            FMA2(acc[1][4], a1, b4); FMA2(acc[1][5], a1, b5);
            FMA2(acc[1][6], a1, b6); FMA2(acc[1][7], a1, b7);
            FMA2(acc[2][0], a2, b0); FMA2(acc[2][1], a2, b1p);
            FMA2(acc[2][2], a2, b2); FMA2(acc[2][3], a2, b3);
            FMA2(acc[2][4], a2, b4); FMA2(acc[2][5], a2, b5);
            FMA2(acc[2][6], a2, b6); FMA2(acc[2][7], a2, b7);
            FMA2(acc[3][0], a3, b0); FMA2(acc[3][1], a3, b1p);
            FMA2(acc[3][2], a3, b2); FMA2(acc[3][3], a3, b3);
            FMA2(acc[3][4], a3, b4); FMA2(acc[3][5], a3, b5);
            FMA2(acc[3][6], a3, b6); FMA2(acc[3][7], a3, b7);
        }
        __syncthreads();
    }

    // epilogue: unpack, +bias, relu, store
    float4 bb0 = *(const float4*)&b1[cg * 8];
    float4 bb1 = *(const float4*)&b1[cg * 8 + 4];
    float bv[8] = {bb0.x, bb0.y, bb0.z, bb0.w, bb1.x, bb1.y, bb1.z, bb1.w};
#pragma unroll
    for (int i2 = 0; i2 < 4; i2++) {
        float lo[8], hi[8];
#pragma unroll
        for (int j = 0; j < 8; j++) UNPK2(lo[j], hi[j], acc[i2][j]);
        int r_lo = row0 + rg * 8 + i2 * 2;
        int r_hi = r_lo + 1;
        if (r_lo < cnt) {
            float4 o0, o1;
            o0.x = fmaxf(lo[0] + bv[0], 0.f); o0.y = fmaxf(lo[1] + bv[1], 0.f);
            o0.z = fmaxf(lo[2] + bv[2], 0.f); o0.w = fmaxf(lo[3] + bv[3], 0.f);
            o1.x = fmaxf(lo[4] + bv[4], 0.f); o1.y = fmaxf(lo[5] + bv[5], 0.f);
            o1.z = fmaxf(lo[6] + bv[6], 0.f); o1.w = fmaxf(lo[7] + bv[7], 0.f);
            *(float4*)&g_h[(size_t)r_lo * 128 + cg * 8]     = o0;
            *(float4*)&g_h[(size_t)r_lo * 128 + cg * 8 + 4] = o1;
        }
        if (r_hi < cnt) {
            float4 o0, o1;
            o0.x = fmaxf(hi[0] + bv[0], 0.f); o0.y = fmaxf(hi[1] + bv[1], 0.f);
            o0.z = fmaxf(hi[2] + bv[2], 0.f); o0.w = fmaxf(hi[3] + bv[3], 0.f);
            o1.x = fmaxf(hi[4] + bv[4], 0.f); o1.y = fmaxf(hi[5] + bv[5], 0.f);
            o1.z = fmaxf(hi[6] + bv[6], 0.f); o1.w = fmaxf(hi[7] + bv[7], 0.f);
            *(float4*)&g_h[(size_t)r_hi * 128 + cg * 8]     = o0;
            *(float4*)&g_h[(size_t)r_hi * 128 + cg * 8 + 4] = o1;
        }
    }
}

// -------------------------------- layer-2 (256 pooled rows) + weighting
__global__ void __launch_bounds__(256) k_pool(const float* __restrict__ x,
                                              const int* __restrict__ pool,
                                              const int* __restrict__ ei,
                                              const float* __restrict__ W2,
                                              const float* __restrict__ root2,
                                              const float* __restrict__ b2) {
    __shared__ float cs[KC];
    __shared__ float red[256];
    const float4* h4 = (const float4*)g_h;
    int p = pool[blockIdx.x];
    int t = threadIdx.x;
    int lane = t & 31, w = t >> 5;   // 8 warps == 8 relations

    {
        int r = w;
        int ptr = g_head[r * NN + p];
        int c = 0;
        float4 acc = make_float4(0.f, 0.f, 0.f, 0.f);
        while (ptr >= 0) {
            int src = ei[ptr];
            int ci = g_cid[src];
            float4 hv = h4[ci * 32 + lane];
            acc.x += hv.x; acc.y += hv.y; acc.z += hv.z; acc.w += hv.w;
            c++;
            ptr = g_next[ptr];
        }
        if (c > 1) {
            float s = 1.0f / (float)c;
            acc.x *= s; acc.y *= s; acc.z *= s; acc.w *= s;
        }
        *(float4*)&cs[r * 128 + lane * 4] = acc;
    }
    if (t < 128) {
        int cp = g_cid[p];
        cs[1024 + t] = g_h[(size_t)cp * 128 + t];
    }
    __syncthreads();

    int j = t & 63, q = t >> 6;   // 4-way K split
    float s = 0.f;
    int k0 = q * 288;
#pragma unroll 4
    for (int k = k0; k < k0 + 288; k++) {
        float wv = (k < 1024) ? W2[k * 64 + j] : root2[(k - 1024) * 64 + j];
        s += cs[k] * wv;
    }
    red[t] = s;
    __syncthreads();
    if (t < 64) {
        float o = red[t] + red[t + 64] + red[t + 128] + red[t + 192] + b2[j];
        float wp = 4.f * x[p * 128 + 0] + x[p * 128 + 1] + 2.f * x[p * 128 + 2];
        g_part[blockIdx.x * 64 + j] = o * wp;
        if (j == 0) g_wp[blockIdx.x] = wp;
    }
}

// fixed-order final reduction (deterministic)
__global__ void k_final(float* __restrict__ out) {
    int j = threadIdx.x;   // 64
    float acc = 0.f;
    for (int i = 0; i < NP; i++) acc += g_part[i * 64 + j];
    float ws = 0.f;
    for (int i = 0; i < NP; i++) ws += g_wp[i];
    out[j] = acc / (ws + 1e-9f);
}

// ---------------------------------------------------------------- launch
extern "C" void kernel_launch(void* const* d_in, const int* in_sizes, int n_in,
                              void* d_out, int out_size) {
    const float* x     = (const float*)d_in[0];
    const int*   ei    = (const int*)  d_in[1];   // [2, NE]: src row 0, dst row 1
    const int*   et    = (const int*)  d_in[2];
    const int*   pool  = (const int*)  d_in[3];
    const float* W1    = (const float*)d_in[4];
    const float* root1 = (const float*)d_in[5];
    const float* b1    = (const float*)d_in[6];
    const float* W2    = (const float*)d_in[7];
    const float* root2 = (const float*)d_in[8];
    const float* b2    = (const float*)d_in[9];
    float* out = (float*)d_out;
    (void)in_sizes; (void)n_in; (void)out_size;

    k_init     <<<(NR * NN + 255) / 256, 256>>>();
    k_mark_pool<<<1, NP>>>(pool);
    k_mark_src <<<(NE + 255) / 256, 256>>>(ei);
    k_compact  <<<(NN + 255) / 256, 256>>>();
    k_build    <<<(NE + 255) / 256, 256>>>(ei, et);
    k_agg1     <<<1024, 256>>>(x, ei);
    k_gemm1    <<<CAP / 64, 128>>>(W1, root1, b1);
    k_pool     <<<NP, 256>>>(x, pool, ei, W2, root2, b2);
    k_final    <<<1, 64>>>(out);
}